// round 16
// baseline (speedup 1.0000x reference)
#include <cuda_runtime.h>

// FeatureFuser: out = sigmoid( last-write-wins(sampling_map, refined[k] over window_k) )
// B=8, TOP_K=4, C=32, H=W=256, GRID=4 (cell 64x64), WINDOW=3 cells (192x192, clipped).
//
// Per output pixel exactly one source is read: refined[b, k_win, c, h, w] where
// k_win = max k whose window contains (h,w), else sampling_map[b,c,h,w].
//
// R16: the untested matrix cell — direct STG stores with L2::evict_first
// policy + register-path loads with L2::evict_last, NO SMEM staging / BAR /
// TMA. Removes per-block: 4 STS.128/thread, __syncthreads (4-warp arrival
// skew), proxy fence, serialized 1-thread TMA issue — i.e. the double
// handling of every output byte. LSU takes 4 extra STG.128/thread (L1 at 44%
// has headroom). Block size 128 = the R14/R15-measured optimum.
//
// Policies (proven individually):
//  - loads: ld.global.nc + L2::evict_last  (67 MB read set repeats per graph
//    replay and fits in 126 MB L2)
//  - stores: st.global + L2::evict_first   (output never re-read)
//
// w4 invariant per thread -> x-predicates and base pointers hoisted.
// regions arrive as int32 (JAX x64 disabled downcasts the int64 request).

#define B_      8
#define K_      4
#define C_      32
#define H_      256
#define W_      256
#define W4_     (W_/4)
#define PLANE4  (H_*W_/4)      // 16384 float4s per (b,c) plane
#define THREADS 128
#define V_      4              // float4s per thread, warp-strided
#define TILE4_  (THREADS*V_)   // 512 float4s per block

__device__ __forceinline__ float fast_sigmoid(float x) {
    float t;
    asm("tanh.approx.f32 %0, %1;" : "=f"(t) : "f"(0.5f * x));
    return fmaf(0.5f, t, 0.5f);
}

__device__ __forceinline__ float4 ldg_evict_last(const float4* p, unsigned long long pol) {
    float4 v;
    asm volatile("ld.global.nc.L2::cache_hint.v4.f32 {%0,%1,%2,%3}, [%4], %5;"
                 : "=f"(v.x), "=f"(v.y), "=f"(v.z), "=f"(v.w)
                 : "l"(p), "l"(pol));
    return v;
}

__device__ __forceinline__ void stg_evict_first(float4* p, float4 v, unsigned long long pol) {
    asm volatile("st.global.L2::cache_hint.v4.f32 [%0], {%1,%2,%3,%4}, %5;"
                 :: "l"(p), "f"(v.x), "f"(v.y), "f"(v.z), "f"(v.w), "l"(pol)
                 : "memory");
}

__global__ void __launch_bounds__(THREADS, 16)
feature_fuser_kernel(const float* __restrict__ smap,
                     const float* __restrict__ rmap,
                     const int* __restrict__ regions,
                     float* __restrict__ out)
{
    const int tid = threadIdx.x;
    const int blockBase = blockIdx.x * TILE4_;       // float4 index
    const int w4  = (blockBase + tid) & (W4_ - 1);   // invariant per thread
    const int bc = blockBase >> 14;                  // uniform per block (32 blocks/plane)
    const int c  = bc & (C_ - 1);
    const int b  = bc >> 5;
    const int hbase = ((blockBase + tid) >> 6) & (H_ - 1);   // threads span 2 rows

    unsigned long long pol_last, pol_first;
    asm volatile("createpolicy.fractional.L2::evict_last.b64 %0, 1.0;"  : "=l"(pol_last));
    asm volatile("createpolicy.fractional.L2::evict_first.b64 %0, 1.0;" : "=l"(pol_first));

    // Hoisted per-k state: y-range and x-predicate (x fixed per thread).
    int ys[K_]; unsigned ylen[K_]; bool xok[K_];
    #pragma unroll
    for (int k = 0; k < K_; ++k) {
        ys[k]   = __ldg(&regions[(b * K_ + k) * 2 + 0]) << 6;
        int xs4 =  __ldg(&regions[(b * K_ + k) * 2 + 1]) << 4;   // float4 units
        ylen[k] = (unsigned)(min(ys[k] + 192, H_) - ys[k]);
        xok[k]  = (unsigned)(w4 - xs4) < (unsigned)(min(xs4 + 48, W4_) - xs4);
    }

    // Per-k source base pointers with w4 folded in.
    const float4* s4 = reinterpret_cast<const float4*>(smap) + (size_t)bc * PLANE4 + w4;
    const float4* r4 = reinterpret_cast<const float4*>(rmap)
                     + ((size_t)(b * K_) * C_ + c) * PLANE4 + w4;

    float4 v[V_];
    #pragma unroll
    for (int i = 0; i < V_; ++i) {
        int h = hbase + 2 * i;                       // 128 threads cover 2 rows/iter
        const float4* p = s4;
        #pragma unroll
        for (int k = 0; k < K_; ++k) {               // ascending: last write wins
            bool inside = xok[k] & ((unsigned)(h - ys[k]) < ylen[k]);
            const float4* pk = r4 + (size_t)k * (C_ * PLANE4);
            p = inside ? pk : p;
        }
        v[i] = ldg_evict_last(p + h * W4_, pol_last);   // MLP=4, front-batched
    }

    float4* o4 = reinterpret_cast<float4*>(out) + blockBase + tid;
    #pragma unroll
    for (int i = 0; i < V_; ++i) {
        v[i].x = fast_sigmoid(v[i].x);
        v[i].y = fast_sigmoid(v[i].y);
        v[i].z = fast_sigmoid(v[i].z);
        v[i].w = fast_sigmoid(v[i].w);
        stg_evict_first(&o4[i * THREADS], v[i], pol_first);
    }
}

extern "C" void kernel_launch(void* const* d_in, const int* in_sizes, int n_in,
                              void* d_out, int out_size)
{
    const float* smap    = (const float*)d_in[0];
    const float* rmap    = (const float*)d_in[1];
    const int*   regions = (const int*)d_in[2];
    float*       out     = (float*)d_out;

    const int total4 = B_ * C_ * H_ * W_ / 4;        // 4,194,304 float4s
    const int blocks = total4 / TILE4_;              // 8192
    feature_fuser_kernel<<<blocks, THREADS>>>(smap, rmap, regions, out);
}